// round 1
// baseline (speedup 1.0000x reference)
#include <cuda_runtime.h>
#include <math.h>

#define NPTS  768
#define NHALF 384
#define DDIM  64
#define NPER  200
#define NKER  4
#define PSLOTS 256   // padded permutation slots (4 tiles of 64)

// ---------------- scratch (device globals; no allocation) ----------------
__device__ float g_Zsq[NPTS];
__device__ float g_K[NKER][NPTS * NPTS];        // 9.44 MB, L2-resident
__device__ float g_rL[NKER][NPTS];              // row sums over cols [0,384)
__device__ float g_rR[NKER][NPTS];              // row sums over cols [384,768)
__device__ float g_row[NKER][NPTS];             // full row sums
__device__ float g_col[NKER][NPTS];             // full col sums
__device__ float g_diag[NKER][NPTS];
__device__ float g_mfT[NPTS][PSLOTS];           // mask transposed: mfT[a][p] = (a in A_p)
__device__ float g_Q[NKER][NPER][NPTS];         // Q[k][p][b] = sum_{a in A_p} K[k][a][b]
__device__ float g_S[NKER];                     // total sum of K
__device__ float g_Dtot[NKER];                  // total diag sum

// ---------------- helpers ----------------
__device__ __forceinline__ float warpred(float v) {
    #pragma unroll
    for (int o = 16; o > 0; o >>= 1) v += __shfl_down_sync(0xffffffffu, v, o);
    return v;
}

// block reduction; result valid on tid 0 only. sm must hold >= nwarps floats.
__device__ __forceinline__ float blockred(float v, float* sm) {
    __syncthreads();
    int tid = threadIdx.x;
    v = warpred(v);
    if ((tid & 31) == 0) sm[tid >> 5] = v;
    __syncthreads();
    float r = 0.f;
    if (tid == 0) {
        int nw = (blockDim.x + 31) >> 5;
        for (int w = 0; w < nw; w++) r += sm[w];
    }
    return r;
}

// ---------------- kernel 0: squared norms of Z = [X; Y] ----------------
__global__ void k_zsq(const float* __restrict__ X, const float* __restrict__ Y) {
    int i = blockIdx.x * blockDim.x + threadIdx.x;
    if (i >= NPTS) return;
    const float* z = (i < NHALF) ? (X + i * DDIM) : (Y + (i - NHALF) * DDIM);
    float s = 0.f;
    #pragma unroll
    for (int d = 0; d < DDIM; d++) { float v = z[d]; s += v * v; }
    g_Zsq[i] = s;
}

// ---------------- kernel 1: 4 kernel matrices, 64x64 tiles ----------------
__global__ void k_pairK(const float* __restrict__ X, const float* __restrict__ Y,
                        const float* __restrict__ bw) {
    __shared__ float Zi[64][65];
    __shared__ float Zj[64][65];
    const int i0 = blockIdx.y * 64, j0 = blockIdx.x * 64;
    const int tid = threadIdx.x;

    for (int idx = tid; idx < 64 * 64; idx += 256) {
        int r = idx >> 6, d = idx & 63;
        int gi = i0 + r;
        Zi[r][d] = (gi < NHALF) ? X[gi * DDIM + d] : Y[(gi - NHALF) * DDIM + d];
        int gj = j0 + r;
        Zj[r][d] = (gj < NHALF) ? X[gj * DDIM + d] : Y[(gj - NHALF) * DDIM + d];
    }
    __syncthreads();

    const int tx = tid & 15, ty = tid >> 4;   // 16x16 threads, each 4x4 outputs
    float acc[4][4] = {};
    #pragma unroll 4
    for (int d = 0; d < 64; d++) {
        float a0 = Zi[ty * 4 + 0][d], a1 = Zi[ty * 4 + 1][d];
        float a2 = Zi[ty * 4 + 2][d], a3 = Zi[ty * 4 + 3][d];
        float b0 = Zj[tx * 4 + 0][d], b1 = Zj[tx * 4 + 1][d];
        float b2 = Zj[tx * 4 + 2][d], b3 = Zj[tx * 4 + 3][d];
        acc[0][0] += a0 * b0; acc[0][1] += a0 * b1; acc[0][2] += a0 * b2; acc[0][3] += a0 * b3;
        acc[1][0] += a1 * b0; acc[1][1] += a1 * b1; acc[1][2] += a1 * b2; acc[1][3] += a1 * b3;
        acc[2][0] += a2 * b0; acc[2][1] += a2 * b1; acc[2][2] += a2 * b2; acc[2][3] += a2 * b3;
        acc[3][0] += a3 * b0; acc[3][1] += a3 * b1; acc[3][2] += a3 * b2; acc[3][3] += a3 * b3;
    }

    // KERNELS = (gaussian, laplacian, gaussian, laplacian)
    const float ig0 = 1.f / (bw[0] * bw[0]);  // gaussian: exp(-d2/b^2)
    const float il1 = 1.f / bw[1];            // laplacian: exp(-dist/b)
    const float ig2 = 1.f / (bw[2] * bw[2]);
    const float il3 = 1.f / bw[3];

    #pragma unroll
    for (int ii = 0; ii < 4; ii++) {
        const int gi = i0 + ty * 4 + ii;
        const float sqi = g_Zsq[gi];
        float4 v0, v1, v2, v3;
        float* p0 = (float*)&v0; float* p1 = (float*)&v1;
        float* p2 = (float*)&v2; float* p3 = (float*)&v3;
        #pragma unroll
        for (int jj = 0; jj < 4; jj++) {
            const int gj = j0 + tx * 4 + jj;
            float d2 = sqi + g_Zsq[gj] - 2.f * acc[ii][jj];
            d2 = fmaxf(d2, 0.f);
            float dist = sqrtf(d2 + 1e-12f);
            float dd = dist * dist;
            float k0 = __expf(-dd * ig0);
            float k1 = __expf(-dist * il1);
            float k2 = __expf(-dd * ig2);
            float k3 = __expf(-dist * il3);
            if (gi < NHALF && gj == gi + NHALF) { k0 = k1 = k2 = k3 = 0.f; }
            p0[jj] = k0; p1[jj] = k1; p2[jj] = k2; p3[jj] = k3;
        }
        const int base = gi * NPTS + j0 + tx * 4;
        *(float4*)&g_K[0][base] = v0;
        *(float4*)&g_K[1][base] = v1;
        *(float4*)&g_K[2][base] = v2;
        *(float4*)&g_K[3][base] = v3;
    }
}

// ---------------- kernel 2: per-row partial sums + diag ----------------
__global__ void k_rows() {
    const int row = blockIdx.x, kk = blockIdx.y;
    const float* Kr = &g_K[kk][row * NPTS];
    const int tid = threadIdx.x;   // 128 threads
    float sL = 0.f, sR = 0.f;
    for (int j = tid; j < NHALF; j += 128) sL += Kr[j];
    for (int j = NHALF + tid; j < NPTS; j += 128) sR += Kr[j];
    __shared__ float sm[8];
    float tL = blockred(sL, sm);
    float tR = blockred(sR, sm);
    if (tid == 0) {
        g_rL[kk][row] = tL;
        g_rR[kk][row] = tR;
        g_row[kk][row] = tL + tR;
        g_diag[kk][row] = Kr[row];
    }
}

// ---------------- kernel 3: column sums ----------------
__global__ void k_cols() {
    const int c = blockIdx.x * 64 + threadIdx.x;
    const int kk = blockIdx.y;
    float s = 0.f;
    #pragma unroll 8
    for (int i = 0; i < NPTS; i++) s += g_K[kk][i * NPTS + c];
    g_col[kk][c] = s;
}

// ---------------- kernel 4: totals + unpermuted U statistic ----------------
__global__ void k_stats(float* __restrict__ out) {
    const int kk = blockIdx.x;
    const int tid = threadIdx.x;   // 256 threads
    float SXX = 0, SXY = 0, SYX = 0, SYY = 0, tX = 0, tY = 0;
    for (int i = tid; i < NPTS; i += 256) {
        float l = g_rL[kk][i], r = g_rR[kk][i], d = g_diag[kk][i];
        if (i < NHALF) { SXX += l; SXY += r; tX += d; }
        else           { SYX += l; SYY += r; tY += d; }
    }
    __shared__ float sm[8];
    float rSXX = blockred(SXX, sm);
    float rSXY = blockred(SXY, sm);
    float rSYX = blockred(SYX, sm);
    float rSYY = blockred(SYY, sm);
    float rtX  = blockred(tX, sm);
    float rtY  = blockred(tY, sm);
    if (tid == 0) {
        const float inv_nn = 1.f / (384.f * 383.f);
        const float inv_nm = 1.f / (384.f * 384.f);
        float U = (rSXX - rtX) * inv_nn + (rSYY - rtY) * inv_nn - 2.f * rSXY * inv_nm;
        g_S[kk] = rSXX + rSXY + rSYX + rSYY;
        g_Dtot[kk] = rtX + rtY;
        out[kk * (NPER + 1)] = U;
    }
}

// ---------------- kernel 5a/5b: build transposed float mask ----------------
__global__ void k_maskzero() {
    g_mfT[blockIdx.x][threadIdx.x] = 0.f;
}
__global__ void k_maskset(const int* __restrict__ perms) {
    const int p = blockIdx.x;          // 200
    const int j = threadIdx.x;         // 384
    g_mfT[perms[p * NPTS + j]][p] = 1.f;
}

// ---------------- kernel 6: phase 1 masked GEMM  Q = P * K ----------------
// grid (12 col-tiles, 4 p-tiles, 4 kernels); 256 threads (8 warps)
// warp w owns 8 permutation slots; lane owns 2 columns.
__global__ void __launch_bounds__(256) k_phase1() {
    const int bc = blockIdx.x, bp = blockIdx.y, kk = blockIdx.z;
    const int tid = threadIdx.x;
    const int w = tid >> 5, lane = tid & 31;
    const int c0 = bc * 64 + lane * 2;
    const int w8 = w * 8;
    const int pbase = bp * 64 + w8;

    __shared__ float msk[128][64];     // 32 KB
    float acc[8][2] = {};
    const float* __restrict__ Kp = &g_K[kk][0];

    for (int ch = 0; ch < 6; ch++) {
        const int a0 = ch * 128;
        for (int idx = tid; idx < 128 * 64; idx += 256) {
            int ar = idx >> 6, pc = idx & 63;
            msk[ar][pc] = g_mfT[a0 + ar][bp * 64 + pc];
        }
        __syncthreads();
        #pragma unroll 2
        for (int al = 0; al < 128; al++) {
            float2 v = *(const float2*)(Kp + (size_t)(a0 + al) * NPTS + c0);
            float m[8];
            *(float4*)&m[0] = *(const float4*)&msk[al][w8];
            *(float4*)&m[4] = *(const float4*)&msk[al][w8 + 4];
            #pragma unroll
            for (int i = 0; i < 8; i++) {
                acc[i][0] += v.x * m[i];
                acc[i][1] += v.y * m[i];
            }
        }
        __syncthreads();
    }

    #pragma unroll
    for (int i = 0; i < 8; i++) {
        int p = pbase + i;
        if (p < NPER) {
            g_Q[kk][p][c0]     = acc[i][0];
            g_Q[kk][p][c0 + 1] = acc[i][1];
        }
    }
}

// ---------------- kernel 7: phase 2 per-perm combine ----------------
__global__ void k_phase2(const int* __restrict__ perms, float* __restrict__ out) {
    const int p = blockIdx.x, kk = blockIdx.y;
    const int tid = threadIdx.x;   // 128 threads
    const float* __restrict__ Qp = &g_Q[kk][p][0];
    const float* __restrict__ Kp = &g_K[kk][0];

    float sQ = 0, sR = 0, sC = 0, sD = 0, sX = 0;
    for (int j = tid; j < NHALF; j += 128) {
        int a = perms[p * NPTS + j];
        int b = perms[p * NPTS + NHALF + j];
        sQ += Qp[a];               // contributes to sAA = sum_{b in A} Q[p][b]
        sR += g_row[kk][a];
        sC += g_col[kk][a];
        sD += g_diag[kk][a];
        sX += Kp[(size_t)a * NPTS + b];   // cross term sum_i K[A_i, B_i]
    }
    __shared__ float sm[8];
    float sAA   = blockred(sQ, sm);
    float sumRA = blockred(sR, sm);
    float sumCA = blockred(sC, sm);
    float sDA   = blockred(sD, sm);
    float cross = blockred(sX, sm);

    if (tid == 0) {
        float S  = g_S[kk];
        float Dt = g_Dtot[kk];
        float sXX = sAA - sDA;
        float sBB = S - sumRA - sumCA + sAA;
        float sYY = sBB - (Dt - sDA);
        float sXY = (sumRA - sAA) - cross;
        const float inv_nn = 1.f / (384.f * 383.f);
        const float inv_nm = 1.f / (384.f * 384.f);
        float Ub = sXX * inv_nn + sYY * inv_nn - 2.f * sXY * inv_nm;
        out[kk * (NPER + 1) + 1 + p] = Ub;
    }
}

// ---------------- launch ----------------
extern "C" void kernel_launch(void* const* d_in, const int* in_sizes, int n_in,
                              void* d_out, int out_size) {
    const float* X     = (const float*)d_in[0];
    const float* Y     = (const float*)d_in[1];
    const float* bw    = (const float*)d_in[2];
    const int*   perms = (const int*)d_in[3];
    float* out = (float*)d_out;

    k_zsq<<<3, 256>>>(X, Y);
    k_pairK<<<dim3(12, 12), 256>>>(X, Y, bw);
    k_rows<<<dim3(NPTS, NKER), 128>>>();
    k_cols<<<dim3(12, NKER), 64>>>();
    k_stats<<<NKER, 256>>>(out);
    k_maskzero<<<NPTS, PSLOTS>>>();
    k_maskset<<<NPER, NHALF>>>(perms);
    k_phase1<<<dim3(12, 4, NKER), 256>>>();
    k_phase2<<<dim3(NPER, NKER), 128>>>(perms, out);
}

// round 2
// speedup vs baseline: 2.0994x; 2.0994x over previous
#include <cuda_runtime.h>
#include <math.h>

#define NPTS  768
#define NHALF 384
#define DDIM  64
#define NPER  200
#define NKER  4
#define PSLOTS 256   // padded permutation slots (4 tiles of 64)

// ---------------- scratch (device globals; no allocation) ----------------
__device__ float g_K[NKER][NPTS * NPTS];        // 9.44 MB, L2-resident
__device__ float g_rL[NKER][NPTS];              // row sums over cols [0,384)
__device__ float g_rR[NKER][NPTS];              // row sums over cols [384,768)
__device__ float g_row[NKER][NPTS];             // full row sums
__device__ float g_colP[NKER][16][NPTS];        // column partial sums (16 row-chunks)
__device__ float g_col[NKER][NPTS];             // full col sums
__device__ float g_diag[NKER][NPTS];
__device__ float g_mfT[NPTS][PSLOTS];           // mask transposed: mfT[a][p] = (a in A_p)
__device__ float g_Q[NKER][2][NPER][NPTS];      // Q split in two a-halves
__device__ float g_S[NKER];                     // total sum of K
__device__ float g_Dtot[NKER];                  // total diag sum

// ---------------- helpers ----------------
__device__ __forceinline__ float warpred(float v) {
    #pragma unroll
    for (int o = 16; o > 0; o >>= 1) v += __shfl_down_sync(0xffffffffu, v, o);
    return v;
}

// block reduction; result valid on tid 0 only. sm must hold >= nwarps floats.
__device__ __forceinline__ float blockred(float v, float* sm) {
    __syncthreads();
    int tid = threadIdx.x;
    v = warpred(v);
    if ((tid & 31) == 0) sm[tid >> 5] = v;
    __syncthreads();
    float r = 0.f;
    if (tid == 0) {
        int nw = (blockDim.x + 31) >> 5;
        for (int w = 0; w < nw; w++) r += sm[w];
    }
    return r;
}

// ---------------- kernel 1: 4 kernel matrices, 64x64 tiles ----------------
__global__ void __launch_bounds__(256) k_pairK(const float* __restrict__ X,
                                               const float* __restrict__ Y,
                                               const float* __restrict__ bw) {
    __shared__ float Zi[64][65];
    __shared__ float Zj[64][65];
    __shared__ float sqi[64], sqj[64];
    const int i0 = blockIdx.y * 64, j0 = blockIdx.x * 64;
    const int tid = threadIdx.x;

    for (int idx = tid; idx < 64 * 64; idx += 256) {
        int r = idx >> 6, d = idx & 63;
        int gi = i0 + r;
        Zi[r][d] = (gi < NHALF) ? X[gi * DDIM + d] : Y[(gi - NHALF) * DDIM + d];
        int gj = j0 + r;
        Zj[r][d] = (gj < NHALF) ? X[gj * DDIM + d] : Y[(gj - NHALF) * DDIM + d];
    }
    __syncthreads();

    // compute squared norms of tile rows from smem
    if (tid < 64) {
        float s = 0.f;
        #pragma unroll
        for (int d = 0; d < 64; d++) { float v = Zi[tid][d]; s += v * v; }
        sqi[tid] = s;
    } else if (tid < 128) {
        int r = tid - 64;
        float s = 0.f;
        #pragma unroll
        for (int d = 0; d < 64; d++) { float v = Zj[r][d]; s += v * v; }
        sqj[r] = s;
    }
    __syncthreads();

    const int tx = tid & 15, ty = tid >> 4;   // 16x16 threads, each 4x4 outputs
    float acc[4][4] = {};
    #pragma unroll 4
    for (int d = 0; d < 64; d++) {
        float a0 = Zi[ty * 4 + 0][d], a1 = Zi[ty * 4 + 1][d];
        float a2 = Zi[ty * 4 + 2][d], a3 = Zi[ty * 4 + 3][d];
        float b0 = Zj[tx * 4 + 0][d], b1 = Zj[tx * 4 + 1][d];
        float b2 = Zj[tx * 4 + 2][d], b3 = Zj[tx * 4 + 3][d];
        acc[0][0] += a0 * b0; acc[0][1] += a0 * b1; acc[0][2] += a0 * b2; acc[0][3] += a0 * b3;
        acc[1][0] += a1 * b0; acc[1][1] += a1 * b1; acc[1][2] += a1 * b2; acc[1][3] += a1 * b3;
        acc[2][0] += a2 * b0; acc[2][1] += a2 * b1; acc[2][2] += a2 * b2; acc[2][3] += a2 * b3;
        acc[3][0] += a3 * b0; acc[3][1] += a3 * b1; acc[3][2] += a3 * b2; acc[3][3] += a3 * b3;
    }

    // KERNELS = (gaussian, laplacian, gaussian, laplacian)
    const float ig0 = 1.f / (bw[0] * bw[0]);  // gaussian: exp(-d2/b^2)
    const float il1 = 1.f / bw[1];            // laplacian: exp(-dist/b)
    const float ig2 = 1.f / (bw[2] * bw[2]);
    const float il3 = 1.f / bw[3];

    #pragma unroll
    for (int ii = 0; ii < 4; ii++) {
        const int gi = i0 + ty * 4 + ii;
        const float si = sqi[ty * 4 + ii];
        float4 v0, v1, v2, v3;
        float* p0 = (float*)&v0; float* p1 = (float*)&v1;
        float* p2 = (float*)&v2; float* p3 = (float*)&v3;
        #pragma unroll
        for (int jj = 0; jj < 4; jj++) {
            const int gj = j0 + tx * 4 + jj;
            float d2 = si + sqj[tx * 4 + jj] - 2.f * acc[ii][jj];
            d2 = fmaxf(d2, 0.f);
            float dist = sqrtf(d2 + 1e-12f);
            float dd = dist * dist;
            float k0 = __expf(-dd * ig0);
            float k1 = __expf(-dist * il1);
            float k2 = __expf(-dd * ig2);
            float k3 = __expf(-dist * il3);
            if (gi < NHALF && gj == gi + NHALF) { k0 = k1 = k2 = k3 = 0.f; }
            p0[jj] = k0; p1[jj] = k1; p2[jj] = k2; p3[jj] = k3;
        }
        const int base = gi * NPTS + j0 + tx * 4;
        *(float4*)&g_K[0][base] = v0;
        *(float4*)&g_K[1][base] = v1;
        *(float4*)&g_K[2][base] = v2;
        *(float4*)&g_K[3][base] = v3;
    }
}

// ---------------- kernel 2: per-row partial sums + diag ----------------
__global__ void k_rows() {
    const int row = blockIdx.x, kk = blockIdx.y;
    const float* Kr = &g_K[kk][row * NPTS];
    const int tid = threadIdx.x;   // 128 threads
    float sL = 0.f, sR = 0.f;
    for (int j = tid; j < NHALF; j += 128) sL += Kr[j];
    for (int j = NHALF + tid; j < NPTS; j += 128) sR += Kr[j];
    __shared__ float sm[8];
    float tL = blockred(sL, sm);
    float tR = blockred(sR, sm);
    if (tid == 0) {
        g_rL[kk][row] = tL;
        g_rR[kk][row] = tR;
        g_row[kk][row] = tL + tR;
        g_diag[kk][row] = Kr[row];
    }
}

// ---------------- kernel 3: column partial sums (coalesced, parallel) ----
// grid (16 row-chunks, 4 kernels), 256 threads; each thread owns 3 columns.
__global__ void __launch_bounds__(256) k_colpart() {
    const int rc = blockIdx.x, kk = blockIdx.y;
    const int tid = threadIdx.x;
    float s0 = 0.f, s1 = 0.f, s2 = 0.f;
    const int i0 = rc * 48;
    #pragma unroll 4
    for (int i = i0; i < i0 + 48; i++) {
        const float* Kr = &g_K[kk][i * NPTS];
        s0 += Kr[tid];
        s1 += Kr[tid + 256];
        s2 += Kr[tid + 512];
    }
    g_colP[kk][rc][tid]       = s0;
    g_colP[kk][rc][tid + 256] = s1;
    g_colP[kk][rc][tid + 512] = s2;
}

// ---------------- kernel 4: col reduce + totals + unpermuted U ----------
__global__ void k_stats(float* __restrict__ out) {
    const int kk = blockIdx.x;
    const int tid = threadIdx.x;   // 256 threads

    // finalize column sums from partials
    for (int c = tid; c < NPTS; c += 256) {
        float s = 0.f;
        #pragma unroll
        for (int rc = 0; rc < 16; rc++) s += g_colP[kk][rc][c];
        g_col[kk][c] = s;
    }

    float SXX = 0, SXY = 0, SYX = 0, SYY = 0, tX = 0, tY = 0;
    for (int i = tid; i < NPTS; i += 256) {
        float l = g_rL[kk][i], r = g_rR[kk][i], d = g_diag[kk][i];
        if (i < NHALF) { SXX += l; SXY += r; tX += d; }
        else           { SYX += l; SYY += r; tY += d; }
    }
    __shared__ float sm[8];
    float rSXX = blockred(SXX, sm);
    float rSXY = blockred(SXY, sm);
    float rSYX = blockred(SYX, sm);
    float rSYY = blockred(SYY, sm);
    float rtX  = blockred(tX, sm);
    float rtY  = blockred(tY, sm);
    if (tid == 0) {
        const float inv_nn = 1.f / (384.f * 383.f);
        const float inv_nm = 1.f / (384.f * 384.f);
        float U = (rSXX - rtX) * inv_nn + (rSYY - rtY) * inv_nn - 2.f * rSXY * inv_nm;
        g_S[kk] = rSXX + rSXY + rSYX + rSYY;
        g_Dtot[kk] = rtX + rtY;
        out[kk * (NPER + 1)] = U;
    }
}

// ---------------- kernel 5a/5b: build transposed float mask ----------------
__global__ void k_maskzero() {
    g_mfT[blockIdx.x][threadIdx.x] = 0.f;
}
__global__ void k_maskset(const int* __restrict__ perms) {
    const int p = blockIdx.x;          // 200
    const int j = threadIdx.x;         // 384
    g_mfT[perms[p * NPTS + j]][p] = 1.f;
}

// ---------------- kernel 6: phase 1 masked GEMM  Q = P * K ----------------
// grid (12 col-tiles, 4 p-tiles, 8 = kernel*2 + a-half); 256 threads (8 warps)
// warp w owns 8 permutation slots; lane owns 2 columns.
__global__ void __launch_bounds__(256) k_phase1() {
    const int bc = blockIdx.x, bp = blockIdx.y;
    const int kk = blockIdx.z >> 1, ah = blockIdx.z & 1;
    const int tid = threadIdx.x;
    const int w = tid >> 5, lane = tid & 31;
    const int c0 = bc * 64 + lane * 2;
    const int w8 = w * 8;
    const int pbase = bp * 64 + w8;
    const bool active = (pbase < NPER);

    __shared__ float msk[128][64];     // 32 KB
    float acc[8][2] = {};
    const float* __restrict__ Kp = &g_K[kk][0];

    const int ch0 = ah * 3;
    for (int ch = ch0; ch < ch0 + 3; ch++) {
        const int a0 = ch * 128;
        // cooperative mask tile load (float4)
        for (int idx = tid; idx < 128 * 16; idx += 256) {
            int ar = idx >> 4, pc4 = (idx & 15) << 2;
            *(float4*)&msk[ar][pc4] =
                *(const float4*)&g_mfT[a0 + ar][bp * 64 + pc4];
        }
        __syncthreads();
        if (active) {
            #pragma unroll 4
            for (int al = 0; al < 128; al++) {
                float2 v = *(const float2*)(Kp + (size_t)(a0 + al) * NPTS + c0);
                float m[8];
                *(float4*)&m[0] = *(const float4*)&msk[al][w8];
                *(float4*)&m[4] = *(const float4*)&msk[al][w8 + 4];
                #pragma unroll
                for (int i = 0; i < 8; i++) {
                    acc[i][0] += v.x * m[i];
                    acc[i][1] += v.y * m[i];
                }
            }
        }
        __syncthreads();
    }

    if (active) {
        #pragma unroll
        for (int i = 0; i < 8; i++) {
            int p = pbase + i;
            if (p < NPER) {
                g_Q[kk][ah][p][c0]     = acc[i][0];
                g_Q[kk][ah][p][c0 + 1] = acc[i][1];
            }
        }
    }
}

// ---------------- kernel 7: phase 2 per-perm combine ----------------
__global__ void k_phase2(const int* __restrict__ perms, float* __restrict__ out) {
    const int p = blockIdx.x, kk = blockIdx.y;
    const int tid = threadIdx.x;   // 128 threads
    const float* __restrict__ Q0 = &g_Q[kk][0][p][0];
    const float* __restrict__ Q1 = &g_Q[kk][1][p][0];
    const float* __restrict__ Kp = &g_K[kk][0];

    float sQ = 0, sR = 0, sC = 0, sD = 0, sX = 0;
    for (int j = tid; j < NHALF; j += 128) {
        int a = perms[p * NPTS + j];
        int b = perms[p * NPTS + NHALF + j];
        sQ += Q0[a] + Q1[a];       // contributes to sAA = sum_{b in A} Q[p][b]
        sR += g_row[kk][a];
        sC += g_col[kk][a];
        sD += g_diag[kk][a];
        sX += Kp[(size_t)a * NPTS + b];   // cross term sum_i K[A_i, B_i]
    }
    __shared__ float sm[8];
    float sAA   = blockred(sQ, sm);
    float sumRA = blockred(sR, sm);
    float sumCA = blockred(sC, sm);
    float sDA   = blockred(sD, sm);
    float cross = blockred(sX, sm);

    if (tid == 0) {
        float S  = g_S[kk];
        float Dt = g_Dtot[kk];
        float sXX = sAA - sDA;
        float sBB = S - sumRA - sumCA + sAA;
        float sYY = sBB - (Dt - sDA);
        float sXY = (sumRA - sAA) - cross;
        const float inv_nn = 1.f / (384.f * 383.f);
        const float inv_nm = 1.f / (384.f * 384.f);
        float Ub = sXX * inv_nn + sYY * inv_nn - 2.f * sXY * inv_nm;
        out[kk * (NPER + 1) + 1 + p] = Ub;
    }
}

// ---------------- launch ----------------
extern "C" void kernel_launch(void* const* d_in, const int* in_sizes, int n_in,
                              void* d_out, int out_size) {
    const float* X     = (const float*)d_in[0];
    const float* Y     = (const float*)d_in[1];
    const float* bw    = (const float*)d_in[2];
    const int*   perms = (const int*)d_in[3];
    float* out = (float*)d_out;

    k_pairK<<<dim3(12, 12), 256>>>(X, Y, bw);
    k_rows<<<dim3(NPTS, NKER), 128>>>();
    k_colpart<<<dim3(16, NKER), 256>>>();
    k_stats<<<NKER, 256>>>(out);
    k_maskzero<<<NPTS, PSLOTS>>>();
    k_maskset<<<NPER, NHALF>>>(perms);
    k_phase1<<<dim3(12, 4, 8), 256>>>();
    k_phase2<<<dim3(NPER, NKER), 128>>>(perms, out);
}

// round 3
// speedup vs baseline: 2.3371x; 1.1132x over previous
#include <cuda_runtime.h>
#include <math.h>

#define NPTS  768
#define NHALF 384
#define DDIM  64
#define NPER  200
#define NKER  4
#define PSLOTS 256   // padded permutation slots (4 tiles of 64)

// ---------------- scratch (device globals; no allocation) ----------------
__device__ float g_K[NKER][NPTS * NPTS];        // 9.44 MB, L2-resident
__device__ float g_rL[NKER][NPTS];              // row sums over cols [0,384)
__device__ float g_rR[NKER][NPTS];              // row sums over cols [384,768)
__device__ float g_row[NKER][NPTS];             // full row sums
__device__ float g_col[NKER][NPTS];             // full col sums (derived from rows)
__device__ float g_diag[NKER][NPTS];
__device__ float g_mfT[NPTS][PSLOTS];           // zero-init; maskset writes identical 1s every call
__device__ float g_Q[NKER][2][NPER][NPTS];      // Q split in two a-halves
__device__ float g_S[NKER];                     // total sum of K
__device__ float g_Dtot[NKER];                  // total diag sum

// ---------------- helpers ----------------
__device__ __forceinline__ float warpred(float v) {
    #pragma unroll
    for (int o = 16; o > 0; o >>= 1) v += __shfl_down_sync(0xffffffffu, v, o);
    return v;
}

// packed fp32x2 FMA (Blackwell): d = a*b + d, all 64-bit packed pairs
#define FFMA2(d, a, b) asm("fma.rn.f32x2 %0, %1, %2, %0;" : "+l"(d) : "l"(a), "l"(b))
#define BCAST2(d, x)   asm("mov.b64 %0, {%1, %1};" : "=l"(d) : "r"(__float_as_uint(x)))

// ---------------- kernel 1: 4 kernel matrices, 64x64 tiles ----------------
__global__ void __launch_bounds__(256) k_pairK(const float* __restrict__ X,
                                               const float* __restrict__ Y,
                                               const float* __restrict__ bw) {
    __shared__ float Zi[64][65];
    __shared__ float Zj[64][65];
    __shared__ float sqi[64], sqj[64];
    const int i0 = blockIdx.y * 64, j0 = blockIdx.x * 64;
    const int tid = threadIdx.x;

    for (int idx = tid; idx < 64 * 64; idx += 256) {
        int r = idx >> 6, d = idx & 63;
        int gi = i0 + r;
        Zi[r][d] = (gi < NHALF) ? X[gi * DDIM + d] : Y[(gi - NHALF) * DDIM + d];
        int gj = j0 + r;
        Zj[r][d] = (gj < NHALF) ? X[gj * DDIM + d] : Y[(gj - NHALF) * DDIM + d];
    }
    __syncthreads();

    if (tid < 64) {
        float s = 0.f;
        #pragma unroll
        for (int d = 0; d < 64; d++) { float v = Zi[tid][d]; s += v * v; }
        sqi[tid] = s;
    } else if (tid < 128) {
        int r = tid - 64;
        float s = 0.f;
        #pragma unroll
        for (int d = 0; d < 64; d++) { float v = Zj[r][d]; s += v * v; }
        sqj[r] = s;
    }
    __syncthreads();

    const int tx = tid & 15, ty = tid >> 4;   // 16x16 threads, each 4x4 outputs
    float acc[4][4] = {};
    #pragma unroll 4
    for (int d = 0; d < 64; d++) {
        float a0 = Zi[ty * 4 + 0][d], a1 = Zi[ty * 4 + 1][d];
        float a2 = Zi[ty * 4 + 2][d], a3 = Zi[ty * 4 + 3][d];
        float b0 = Zj[tx * 4 + 0][d], b1 = Zj[tx * 4 + 1][d];
        float b2 = Zj[tx * 4 + 2][d], b3 = Zj[tx * 4 + 3][d];
        acc[0][0] += a0 * b0; acc[0][1] += a0 * b1; acc[0][2] += a0 * b2; acc[0][3] += a0 * b3;
        acc[1][0] += a1 * b0; acc[1][1] += a1 * b1; acc[1][2] += a1 * b2; acc[1][3] += a1 * b3;
        acc[2][0] += a2 * b0; acc[2][1] += a2 * b1; acc[2][2] += a2 * b2; acc[2][3] += a2 * b3;
        acc[3][0] += a3 * b0; acc[3][1] += a3 * b1; acc[3][2] += a3 * b2; acc[3][3] += a3 * b3;
    }

    // KERNELS = (gaussian, laplacian, gaussian, laplacian)
    const float ig0 = 1.f / (bw[0] * bw[0]);
    const float il1 = 1.f / bw[1];
    const float ig2 = 1.f / (bw[2] * bw[2]);
    const float il3 = 1.f / bw[3];

    #pragma unroll
    for (int ii = 0; ii < 4; ii++) {
        const int gi = i0 + ty * 4 + ii;
        const float si = sqi[ty * 4 + ii];
        float4 v0, v1, v2, v3;
        float* p0 = (float*)&v0; float* p1 = (float*)&v1;
        float* p2 = (float*)&v2; float* p3 = (float*)&v3;
        #pragma unroll
        for (int jj = 0; jj < 4; jj++) {
            const int gj = j0 + tx * 4 + jj;
            float d2 = si + sqj[tx * 4 + jj] - 2.f * acc[ii][jj];
            d2 = fmaxf(d2, 0.f);
            float dist = sqrtf(d2 + 1e-12f);
            float dd = dist * dist;
            float k0 = __expf(-dd * ig0);
            float k1 = __expf(-dist * il1);
            float k2 = __expf(-dd * ig2);
            float k3 = __expf(-dist * il3);
            if (gi < NHALF && gj == gi + NHALF) { k0 = k1 = k2 = k3 = 0.f; }
            p0[jj] = k0; p1[jj] = k1; p2[jj] = k2; p3[jj] = k3;
        }
        const int base = gi * NPTS + j0 + tx * 4;
        *(float4*)&g_K[0][base] = v0;
        *(float4*)&g_K[1][base] = v1;
        *(float4*)&g_K[2][base] = v2;
        *(float4*)&g_K[3][base] = v3;
    }
}

// ---------------- kernel 2: row sums + diag + derived col sums ----------
// col[c] = row[c] + K[c+384][c]  (c<384)   [symmetry + one-sided zeroing]
// col[c] = row[c] - K[c][c-384]  (c>=384)
__global__ void k_rows() {
    const int row = blockIdx.x, kk = blockIdx.y;
    const float* __restrict__ Kr = &g_K[kk][row * NPTS];
    const int tid = threadIdx.x;   // 128 threads
    float sL = 0.f, sR = 0.f;
    #pragma unroll
    for (int j = tid; j < NHALF; j += 128) sL += Kr[j];
    #pragma unroll
    for (int j = NHALF + tid; j < NPTS; j += 128) sR += Kr[j];
    __shared__ float smL[4], smR[4];
    sL = warpred(sL); sR = warpred(sR);
    if ((tid & 31) == 0) { smL[tid >> 5] = sL; smR[tid >> 5] = sR; }
    __syncthreads();
    if (tid == 0) {
        float tL = smL[0] + smL[1] + smL[2] + smL[3];
        float tR = smR[0] + smR[1] + smR[2] + smR[3];
        g_rL[kk][row] = tL;
        g_rR[kk][row] = tR;
        float rs = tL + tR;
        g_row[kk][row] = rs;
        g_diag[kk][row] = Kr[row];
        if (row < NHALF) {
            float z = g_K[kk][(size_t)(NHALF + row) * NPTS + row];
            g_col[kk][row] = rs + z;
        } else {
            float z = Kr[row - NHALF];
            g_col[kk][row] = rs - z;
        }
    }
}

// ---------------- kernel 3: totals + unpermuted U (single sync) ---------
__global__ void k_stats(float* __restrict__ out) {
    const int kk = blockIdx.x;
    const int tid = threadIdx.x;   // 256 threads
    float s[6] = {0, 0, 0, 0, 0, 0};   // SXX, SXY, SYX, SYY, tX, tY
    for (int i = tid; i < NPTS; i += 256) {
        float l = g_rL[kk][i], r = g_rR[kk][i], d = g_diag[kk][i];
        if (i < NHALF) { s[0] += l; s[1] += r; s[4] += d; }
        else           { s[2] += l; s[3] += r; s[5] += d; }
    }
    __shared__ float sm[6][8];
    #pragma unroll
    for (int q = 0; q < 6; q++) {
        float v = warpred(s[q]);
        if ((tid & 31) == 0) sm[q][tid >> 5] = v;
    }
    __syncthreads();
    if (tid == 0) {
        float r[6];
        #pragma unroll
        for (int q = 0; q < 6; q++) {
            float a = 0.f;
            #pragma unroll
            for (int w = 0; w < 8; w++) a += sm[q][w];
            r[q] = a;
        }
        const float inv_nn = 1.f / (384.f * 383.f);
        const float inv_nm = 1.f / (384.f * 384.f);
        float U = (r[0] - r[4]) * inv_nn + (r[3] - r[5]) * inv_nn - 2.f * r[1] * inv_nm;
        g_S[kk] = r[0] + r[1] + r[2] + r[3];
        g_Dtot[kk] = r[4] + r[5];
        out[kk * (NPER + 1)] = U;
    }
}

// ---------------- kernel 4: set mask (globals are zero-initialized) -----
__global__ void k_maskset(const int* __restrict__ perms) {
    const int p = blockIdx.x;          // 200
    const int j = threadIdx.x;         // 384
    g_mfT[perms[p * NPTS + j]][p] = 1.f;
}

// ---------------- kernel 5: phase 1 masked GEMM via fma.rn.f32x2 --------
// grid (12 col-tiles, 4 p-tiles, kernel*2 + a-half); 256 threads (8 warps)
// warp w owns 8 perm slots (as 4 packed pairs); lane owns 2 columns.
__global__ void __launch_bounds__(256) k_phase1() {
    const int bc = blockIdx.x, bp = blockIdx.y;
    const int kk = blockIdx.z >> 1, ah = blockIdx.z & 1;
    const int tid = threadIdx.x;
    const int w = tid >> 5, lane = tid & 31;
    const int c0 = bc * 64 + lane * 2;
    const int w8 = w * 8;
    const int pbase = bp * 64 + w8;
    const bool active = (pbase < NPER);

    __shared__ __align__(16) float msk[128][64];     // 32 KB
    unsigned long long acc[4][2] = {};               // [perm-pair][col], packed f32x2
    const float* __restrict__ Kp = &g_K[kk][0];

    const int ch0 = ah * 3;
    for (int ch = ch0; ch < ch0 + 3; ch++) {
        const int a0 = ch * 128;
        for (int idx = tid; idx < 128 * 16; idx += 256) {
            int ar = idx >> 4, pc4 = (idx & 15) << 2;
            *(float4*)&msk[ar][pc4] =
                *(const float4*)&g_mfT[a0 + ar][bp * 64 + pc4];
        }
        __syncthreads();
        if (active) {
            #pragma unroll 4
            for (int al = 0; al < 128; al++) {
                float2 v = *(const float2*)(Kp + (size_t)(a0 + al) * NPTS + c0);
                unsigned long long vx, vy;
                BCAST2(vx, v.x);
                BCAST2(vy, v.y);
                ulonglong2 mA = *(const ulonglong2*)&msk[al][w8];       // (m0,m1),(m2,m3)
                ulonglong2 mB = *(const ulonglong2*)&msk[al][w8 + 4];   // (m4,m5),(m6,m7)
                FFMA2(acc[0][0], mA.x, vx);  FFMA2(acc[0][1], mA.x, vy);
                FFMA2(acc[1][0], mA.y, vx);  FFMA2(acc[1][1], mA.y, vy);
                FFMA2(acc[2][0], mB.x, vx);  FFMA2(acc[2][1], mB.x, vy);
                FFMA2(acc[3][0], mB.y, vx);  FFMA2(acc[3][1], mB.y, vy);
            }
        }
        __syncthreads();
    }

    if (active) {
        #pragma unroll
        for (int j = 0; j < 4; j++) {
            #pragma unroll
            for (int c = 0; c < 2; c++) {
                unsigned int lo, hi;
                asm("mov.b64 {%0, %1}, %2;" : "=r"(lo), "=r"(hi) : "l"(acc[j][c]));
                int p0 = pbase + 2 * j, p1 = p0 + 1;
                if (p0 < NPER) g_Q[kk][ah][p0][c0 + c] = __uint_as_float(lo);
                if (p1 < NPER) g_Q[kk][ah][p1][c0 + c] = __uint_as_float(hi);
            }
        }
    }
}

// ---------------- kernel 6: phase 2 per-perm combine ----------------
__global__ void k_phase2(const int* __restrict__ perms, float* __restrict__ out) {
    const int p = blockIdx.x, kk = blockIdx.y;
    const int tid = threadIdx.x;   // 128 threads
    const float* __restrict__ Q0 = &g_Q[kk][0][p][0];
    const float* __restrict__ Q1 = &g_Q[kk][1][p][0];
    const float* __restrict__ Kp = &g_K[kk][0];

    float s[5] = {0, 0, 0, 0, 0};   // sQ, sR, sC, sD, sX
    for (int j = tid; j < NHALF; j += 128) {
        int a = perms[p * NPTS + j];
        int b = perms[p * NPTS + NHALF + j];
        s[0] += Q0[a] + Q1[a];
        s[1] += g_row[kk][a];
        s[2] += g_col[kk][a];
        s[3] += g_diag[kk][a];
        s[4] += Kp[(size_t)a * NPTS + b];
    }
    __shared__ float sm[5][4];
    #pragma unroll
    for (int q = 0; q < 5; q++) {
        float v = warpred(s[q]);
        if ((tid & 31) == 0) sm[q][tid >> 5] = v;
    }
    __syncthreads();
    if (tid == 0) {
        float r[5];
        #pragma unroll
        for (int q = 0; q < 5; q++)
            r[q] = sm[q][0] + sm[q][1] + sm[q][2] + sm[q][3];
        float sAA = r[0], sumRA = r[1], sumCA = r[2], sDA = r[3], cross = r[4];
        float S  = g_S[kk];
        float Dt = g_Dtot[kk];
        float sXX = sAA - sDA;
        float sBB = S - sumRA - sumCA + sAA;
        float sYY = sBB - (Dt - sDA);
        float sXY = (sumRA - sAA) - cross;
        const float inv_nn = 1.f / (384.f * 383.f);
        const float inv_nm = 1.f / (384.f * 384.f);
        float Ub = sXX * inv_nn + sYY * inv_nn - 2.f * sXY * inv_nm;
        out[kk * (NPER + 1) + 1 + p] = Ub;
    }
}

// ---------------- launch ----------------
extern "C" void kernel_launch(void* const* d_in, const int* in_sizes, int n_in,
                              void* d_out, int out_size) {
    const float* X     = (const float*)d_in[0];
    const float* Y     = (const float*)d_in[1];
    const float* bw    = (const float*)d_in[2];
    const int*   perms = (const int*)d_in[3];
    float* out = (float*)d_out;

    k_maskset<<<NPER, NHALF>>>(perms);
    k_pairK<<<dim3(12, 12), 256>>>(X, Y, bw);
    k_rows<<<dim3(NPTS, NKER), 128>>>();
    k_stats<<<NKER, 256>>>(out);
    k_phase1<<<dim3(12, 4, 8), 256>>>();
    k_phase2<<<dim3(NPER, NKER), 128>>>(perms, out);
}